// round 12
// baseline (speedup 1.0000x reference)
#include <cuda_runtime.h>

#define BB 2
#define HH 64
#define WW 64
#define CC 128
#define NHEAD 4
#define HD 32
#define KWIN 7
#define MROWS (BB*HH*WW)          /* 8192 */
#define SCALE 0.17677669529663687f /* 32^-0.5 */

// Scratch (allocation-free rule: device globals). All tf32 bit patterns.
__device__ unsigned g_x[MROWS*CC];
__device__ unsigned g_wqkv[CC*384];
__device__ unsigned g_wproj[CC*CC];
__device__ unsigned g_q[MROWS*CC];
__device__ unsigned g_k[MROWS*CC];
__device__ unsigned g_v[MROWS*CC];
__device__ unsigned g_att[MROWS*CC];

__device__ __forceinline__ unsigned f2tf(float f) {
    unsigned r;
    asm("cvt.rna.tf32.f32 %0, %1;" : "=r"(r) : "f"(f));
    return r;
}

__device__ __forceinline__ void mma_tf32(float c[4],
    unsigned a0, unsigned a1, unsigned a2, unsigned a3,
    unsigned b0, unsigned b1) {
    asm volatile(
        "mma.sync.aligned.m16n8k8.row.col.f32.tf32.tf32.f32 "
        "{%0,%1,%2,%3}, {%4,%5,%6,%7}, {%8,%9}, {%0,%1,%2,%3};"
        : "+f"(c[0]), "+f"(c[1]), "+f"(c[2]), "+f"(c[3])
        : "r"(a0), "r"(a1), "r"(a2), "r"(a3), "r"(b0), "r"(b1));
}

__device__ __forceinline__ void cp16(void* smem, const void* gmem) {
    unsigned s = (unsigned)__cvta_generic_to_shared(smem);
    asm volatile("cp.async.cg.shared.global [%0], [%1], 16;" :: "r"(s), "l"(gmem));
}
__device__ __forceinline__ void cp_commit() {
    asm volatile("cp.async.commit_group;");
}
template<int N> __device__ __forceinline__ void cp_wait() {
    asm volatile("cp.async.wait_group %0;" :: "n"(N));
}

// ---------------------------------------------------------------------------
// Pre-convert x / w_qkv / w_proj to tf32 (rna) once.
// Grid 1024 x 256, float4-granular.
// ---------------------------------------------------------------------------
__global__ __launch_bounds__(256)
void cvt_inputs(const float4* __restrict__ x,
                const float4* __restrict__ wqkv,
                const float4* __restrict__ wproj) {
    const int i = blockIdx.x * 256 + threadIdx.x;   // float4 index
    float4 v = x[i];
    *(uint4*)&g_x[i * 4] = make_uint4(f2tf(v.x), f2tf(v.y), f2tf(v.z), f2tf(v.w));
    if (i < CC * 384 / 4) {
        float4 w = wqkv[i];
        *(uint4*)&g_wqkv[i * 4] = make_uint4(f2tf(w.x), f2tf(w.y), f2tf(w.z), f2tf(w.w));
    }
    if (i < CC * CC / 4) {
        float4 w = wproj[i];
        *(uint4*)&g_wproj[i * 4] = make_uint4(f2tf(w.x), f2tf(w.y), f2tf(w.z), f2tf(w.w));
    }
}

// ---------------------------------------------------------------------------
// tf32 GEMM v4: 128x64 tile, 256 threads (proven shape), cp.async-pipelined
// double-buffered staging of pre-converted tf32 operands. Dynamic smem 55.3KB.
// MODE 0: A=g_x, W=g_wqkv, split epilogue -> tf32 g_q (scaled), g_k, g_v.
// MODE 1: A=g_att, W=g_wproj, out = fp32 result + bias.
// ---------------------------------------------------------------------------
#define ASTRIDE 36
#define BSTRIDE 72
#define ABUF (128*ASTRIDE)
#define BBUF (32*BSTRIDE)
#define GEMM_DSM ((2*ABUF + 2*BBUF) * 4)   /* 55296 bytes */

template<int NTOT, int MODE>
__global__ __launch_bounds__(256)
void gemm_tc(const float* __restrict__ bias, float* __restrict__ out) {
    extern __shared__ __align__(16) unsigned dsm[];
    unsigned* As = dsm;                // [2][128*36]
    unsigned* Bs = dsm + 2 * ABUF;     // [2][32*72]

    const unsigned* Ap = (MODE == 1) ? g_att : g_x;
    const unsigned* Wp = (MODE == 1) ? g_wproj : g_wqkv;

    const int tid  = threadIdx.x;
    const int lane = tid & 31;
    const int wid  = tid >> 5;
    const int warpM = wid & 3;
    const int warpN = wid >> 2;
    const int grp = lane >> 2;
    const int tig = lane & 3;
    const int rowbase = blockIdx.x * 128;
    const int colbase = blockIdx.y * 64;

    const int am = tid >> 3;            // 0..31 (+32j)  -> m rows via i>>3
    const int ak = (tid & 7) * 4;
    const int bk = tid >> 4;            // 0..15 (+16j)
    const int bn = (tid & 15) * 4;

    auto issue = [&](int kc, int buf) {
        const int k0 = kc * 32;
        unsigned* Ab = As + buf * ABUF;
        #pragma unroll
        for (int j = 0; j < 4; ++j) {
            const int m = am + j * 32;
            cp16(Ab + m * ASTRIDE + ak, Ap + (rowbase + m) * 128 + k0 + ak);
        }
        unsigned* Bb = Bs + buf * BBUF;
        #pragma unroll
        for (int j = 0; j < 2; ++j) {
            const int k = bk + j * 16;
            cp16(Bb + k * BSTRIDE + bn, Wp + (k0 + k) * NTOT + colbase + bn);
        }
        cp_commit();
    };

    float acc[2][4][4] = {};

    issue(0, 0);
    issue(1, 1);

    #pragma unroll
    for (int kc = 0; kc < 4; ++kc) {
        if (kc < 3) cp_wait<1>(); else cp_wait<0>();
        __syncthreads();

        const unsigned* Ab = As + (kc & 1) * ABUF;
        const unsigned* Bb = Bs + (kc & 1) * BBUF;
        #pragma unroll
        for (int ks = 0; ks < 4; ++ks) {
            const int kk = ks * 8;
            unsigned a[2][4], b[4][2];
            #pragma unroll
            for (int mf = 0; mf < 2; ++mf) {
                const int r = warpM * 32 + mf * 16 + grp;
                a[mf][0] = Ab[r * ASTRIDE + kk + tig];
                a[mf][1] = Ab[(r + 8) * ASTRIDE + kk + tig];
                a[mf][2] = Ab[r * ASTRIDE + kk + tig + 4];
                a[mf][3] = Ab[(r + 8) * ASTRIDE + kk + tig + 4];
            }
            #pragma unroll
            for (int nf = 0; nf < 4; ++nf) {
                const int c = warpN * 32 + nf * 8 + grp;
                b[nf][0] = Bb[(kk + tig) * BSTRIDE + c];
                b[nf][1] = Bb[(kk + tig + 4) * BSTRIDE + c];
            }
            #pragma unroll
            for (int mf = 0; mf < 2; ++mf)
                #pragma unroll
                for (int nf = 0; nf < 4; ++nf)
                    mma_tf32(acc[mf][nf],
                             a[mf][0], a[mf][1], a[mf][2], a[mf][3],
                             b[nf][0], b[nf][1]);
        }
        __syncthreads();
        if (kc < 2) issue(kc + 2, kc & 1);
    }

    #pragma unroll
    for (int mf = 0; mf < 2; ++mf) {
        #pragma unroll
        for (int nf = 0; nf < 4; ++nf) {
            const int colL = colbase + warpN * 32 + nf * 8 + tig * 2;
            const float bs0 = bias[colL];
            const float bs1 = bias[colL + 1];
            #pragma unroll
            for (int rr = 0; rr < 2; ++rr) {
                const int row = rowbase + warpM * 32 + mf * 16 + grp + rr * 8;
                float v0 = acc[mf][nf][rr * 2 + 0] + bs0;
                float v1 = acc[mf][nf][rr * 2 + 1] + bs1;
                if (MODE == 0) {
                    const int comp  = colL >> 7;
                    const int inner = colL & 127;
                    if (comp == 0)
                        *(uint2*)&g_q[row * CC + inner] = make_uint2(f2tf(v0 * SCALE), f2tf(v1 * SCALE));
                    else if (comp == 1)
                        *(uint2*)&g_k[row * CC + inner] = make_uint2(f2tf(v0), f2tf(v1));
                    else
                        *(uint2*)&g_v[row * CC + inner] = make_uint2(f2tf(v0), f2tf(v1));
                } else {
                    *(float2*)&out[row * NTOT + colL] = make_float2(v0, v1);
                }
            }
        }
    }
}

// ---------------------------------------------------------------------------
// Neighborhood attention v5.2 (Round-11 measured best; only change: g_att is
// written as tf32 bits so the proj GEMM can cp.async it directly).
// ---------------------------------------------------------------------------
#define TTH 4
#define TTW 8
#define NHALO_H 10
#define NHALO_W 14
#define NPX 140
#define NPAD 144
#define SKSN 36

__global__ __launch_bounds__(128)
void natten_tc(const float* __restrict__ rpb) {
    __shared__ __align__(16) unsigned sK[NPAD * SKSN];
    __shared__ __align__(16) unsigned sV[NPAD * SKSN];
    __shared__ float srp[169];
    __shared__ float sl[2][2][16];

    float* sO = (float*)sK;   // alias: sK dead after S-phase barrier

    const int tid  = threadIdx.x;
    const int lane = tid & 31;
    const int wid  = tid >> 5;
    const int mt   = wid >> 1;
    const int half = wid & 1;
    const int grp  = lane >> 2;
    const int tig  = lane & 3;

    const int w0 = blockIdx.x * TTW;
    const int h0 = blockIdx.y * TTH;
    const int nh = blockIdx.z & 3;
    const int b  = blockIdx.z >> 2;
    const int bbase = b << 12;

    int gh0 = h0 - 3; gh0 = gh0 < 0 ? 0 : (gh0 > 64 - NHALO_H ? 64 - NHALO_H : gh0);
    int gw0 = w0 - 3; gw0 = gw0 < 0 ? 0 : (gw0 > 64 - NHALO_W ? 64 - NHALO_W : gw0);

    const int hA = h0 + mt * 2;
    const int hB = hA + 1;
    const int wq = w0 + grp;
    const int pixA = bbase + (hA << 6) + wq;
    const int pixB = pixA + 64;

    unsigned qa[4][4];
    #pragma unroll
    for (int kc = 0; kc < 4; ++kc) {
        const int d = kc * 8 + tig;
        qa[kc][0] = g_q[pixA * CC + nh * 32 + d];
        qa[kc][1] = g_q[pixB * CC + nh * 32 + d];
        qa[kc][2] = g_q[pixA * CC + nh * 32 + d + 4];
        qa[kc][3] = g_q[pixB * CC + nh * 32 + d + 4];
    }

    for (int i = tid; i < 169; i += 128) srp[i] = rpb[nh * 169 + i];

    const uint4* gk4 = (const uint4*)g_k;
    const uint4* gv4 = (const uint4*)g_v;
    for (int i = tid; i < NPX * 8; i += 128) {
        const int px = i >> 3;
        const int f  = i & 7;
        const int r  = px / NHALO_W;
        const int c  = px - r * NHALO_W;
        const int goff = (bbase + ((gh0 + r) << 6) + gw0 + c) * 32 + nh * 8 + f;
        *(uint4*)&sK[px * SKSN + f * 4] = gk4[goff];
        *(uint4*)&sV[px * SKSN + f * 4] = gv4[goff];
    }
    for (int i = tid; i < (NPAD - NPX) * SKSN; i += 128) {
        sK[NPX * SKSN + i] = 0;
        sV[NPX * SKSN + i] = 0;
    }
    __syncthreads();

    float sacc[9][4] = {};
    #pragma unroll
    for (int i = 0; i < 9; ++i) {
        const int n0 = half * 72 + i * 8;
        #pragma unroll
        for (int kc = 0; kc < 4; ++kc) {
            unsigned b0 = sK[(n0 + grp) * SKSN + kc * 8 + tig];
            unsigned b1 = sK[(n0 + grp) * SKSN + kc * 8 + tig + 4];
            mma_tf32(sacc[i], qa[kc][0], qa[kc][1], qa[kc][2], qa[kc][3], b0, b1);
        }
    }

    int hsA = hA - 3; hsA = hsA < 0 ? 0 : (hsA > 57 ? 57 : hsA);
    int hsB = hB - 3; hsB = hsB < 0 ? 0 : (hsB > 57 ? 57 : hsB);
    int wsq = wq - 3; wsq = wsq < 0 ? 0 : (wsq > 57 ? 57 : wsq);

    float e[9][4];
    float lA = 0.f, lB = 0.f;
    #pragma unroll
    for (int i = 0; i < 9; ++i) {
        #pragma unroll
        for (int ee = 0; ee < 2; ++ee) {
            const int n  = half * 72 + i * 8 + 2 * tig + ee;
            const int hr = n / NHALO_W;
            const int wc = n - hr * NHALO_W;
            const int kh = gh0 + hr;
            const int kw = gw0 + wc;
            const bool vw = (kw >= wsq) && (kw <= wsq + 6);
            float eA = 0.f, eB = 0.f;
            if (vw && kh >= hsA && kh <= hsA + 6)
                eA = __expf(sacc[i][ee]     + srp[(kh - hA + 6) * 13 + (kw - wq + 6)]);
            if (vw && kh >= hsB && kh <= hsB + 6)
                eB = __expf(sacc[i][2 + ee] + srp[(kh - hB + 6) * 13 + (kw - wq + 6)]);
            e[i][ee]     = eA;
            e[i][2 + ee] = eB;
            lA += eA;
            lB += eB;
        }
    }
    lA += __shfl_xor_sync(0xffffffffu, lA, 1);
    lA += __shfl_xor_sync(0xffffffffu, lA, 2);
    lB += __shfl_xor_sync(0xffffffffu, lB, 1);
    lB += __shfl_xor_sync(0xffffffffu, lB, 2);
    if (tig == 0) {
        sl[mt][half][grp]     = lA;
        sl[mt][half][grp + 8] = lB;
    }
    __syncthreads();
    const float invA = 1.f / (sl[mt][0][grp]     + sl[mt][1][grp]);
    const float invB = 1.f / (sl[mt][0][grp + 8] + sl[mt][1][grp + 8]);

    float oacc[4][4] = {};
    const int src0 = grp * 4 + (tig >> 1);
    const bool odd = tig & 1;
    #pragma unroll
    for (int i = 0; i < 9; ++i) {
        float p0a = __shfl_sync(0xffffffffu, e[i][0], src0);
        float p0b = __shfl_sync(0xffffffffu, e[i][1], src0);
        float p1a = __shfl_sync(0xffffffffu, e[i][2], src0);
        float p1b = __shfl_sync(0xffffffffu, e[i][3], src0);
        float p2a = __shfl_sync(0xffffffffu, e[i][0], src0 + 2);
        float p2b = __shfl_sync(0xffffffffu, e[i][1], src0 + 2);
        float p3a = __shfl_sync(0xffffffffu, e[i][2], src0 + 2);
        float p3b = __shfl_sync(0xffffffffu, e[i][3], src0 + 2);
        unsigned a0 = f2tf(odd ? p0b : p0a);
        unsigned a1 = f2tf(odd ? p1b : p1a);
        unsigned a2 = f2tf(odd ? p2b : p2a);
        unsigned a3 = f2tf(odd ? p3b : p3a);
        const int kb = half * 72 + i * 8;
        #pragma unroll
        for (int dt = 0; dt < 4; ++dt) {
            unsigned b0 = sV[(kb + tig) * SKSN + dt * 8 + grp];
            unsigned b1 = sV[(kb + tig + 4) * SKSN + dt * 8 + grp];
            mma_tf32(oacc[dt], a0, a1, a2, a3, b0, b1);
        }
    }

    #pragma unroll
    for (int dt = 0; dt < 4; ++dt) {
        const int dc = dt * 8 + tig * 2;
        if (half == 0) {
            sO[mt * 512 + grp * 32 + dc]            = oacc[dt][0];
            sO[mt * 512 + grp * 32 + dc + 1]        = oacc[dt][1];
            sO[mt * 512 + (grp + 8) * 32 + dc]      = oacc[dt][2];
            sO[mt * 512 + (grp + 8) * 32 + dc + 1]  = oacc[dt][3];
        }
    }
    __syncthreads();
    if (half == 1) {
        #pragma unroll
        for (int dt = 0; dt < 4; ++dt) {
            const int dc = dt * 8 + tig * 2;
            float t0 = oacc[dt][0] + sO[mt * 512 + grp * 32 + dc];
            float t1 = oacc[dt][1] + sO[mt * 512 + grp * 32 + dc + 1];
            float t2 = oacc[dt][2] + sO[mt * 512 + (grp + 8) * 32 + dc];
            float t3 = oacc[dt][3] + sO[mt * 512 + (grp + 8) * 32 + dc + 1];
            *(uint2*)&g_att[pixA * CC + nh * 32 + dc] =
                make_uint2(f2tf(t0 * invA), f2tf(t1 * invA));
            *(uint2*)&g_att[pixB * CC + nh * 32 + dc] =
                make_uint2(f2tf(t2 * invB), f2tf(t3 * invB));
        }
    }
}

extern "C" void kernel_launch(void* const* d_in, const int* in_sizes, int n_in,
                              void* d_out, int out_size) {
    (void)in_sizes; (void)n_in; (void)out_size;
    const float* x      = (const float*)d_in[0];
    const float* w_qkv  = (const float*)d_in[1];
    const float* b_qkv  = (const float*)d_in[2];
    const float* rpb    = (const float*)d_in[3];
    const float* w_proj = (const float*)d_in[4];
    const float* b_proj = (const float*)d_in[5];
    float* out = (float*)d_out;

    cudaFuncSetAttribute(gemm_tc<384, 0>,
                         cudaFuncAttributeMaxDynamicSharedMemorySize, GEMM_DSM);
    cudaFuncSetAttribute(gemm_tc<128, 1>,
                         cudaFuncAttributeMaxDynamicSharedMemorySize, GEMM_DSM);

    cvt_inputs<<<MROWS * CC / 4 / 256, 256>>>(
        (const float4*)x, (const float4*)w_qkv, (const float4*)w_proj);

    dim3 g1(MROWS / 128, 384 / 64);
    gemm_tc<384, 0><<<g1, 256, GEMM_DSM>>>(b_qkv, nullptr);

    dim3 gn(WW / TTW, HH / TTH, BB * NHEAD);   // (8, 16, 8)
    natten_tc<<<gn, 128>>>(rpb);

    dim3 g2(MROWS / 128, 128 / 64);
    gemm_tc<128, 1><<<g2, 256, GEMM_DSM>>>(b_proj, out);
}